// round 1
// baseline (speedup 1.0000x reference)
#include <cuda_runtime.h>

#define B_TOT    8192
#define T_LEN    512
#define F_IN     24
#define H_DIM    12
#define CHUNK    8
#define EPB      32           // batch elements per block
#define TPE      4            // threads per element (3 h-rows each)
#define NTHREADS (EPB * TPE)  // 128
#define NCHUNK   (T_LEN / CHUNK)
#define XS_STRIDE 28          // padded floats per (tt, elem): 28*e mod 32 hits all banks
#define XS_BUF_FLOATS (CHUNK * EPB * XS_STRIDE)
#define SMEM_BYTES (2 * XS_BUF_FLOATS * 4)

__device__ __forceinline__ unsigned smem_u32(const void* p) {
    return (unsigned)__cvta_generic_to_shared(p);
}
__device__ __forceinline__ void cp_async16(unsigned dst, const void* src) {
    asm volatile("cp.async.cg.shared.global [%0], [%1], 16;\n" :: "r"(dst), "l"(src));
}
__device__ __forceinline__ void cp_commit() {
    asm volatile("cp.async.commit_group;\n" ::: "memory");
}
template <int N> __device__ __forceinline__ void cp_wait() {
    asm volatile("cp.async.wait_group %0;\n" :: "n"(N) : "memory");
}

// tanh via exp: |err| ~1e-6, 2 MUFU ops instead of ~20-instr accurate tanhf.
__device__ __forceinline__ float tanh_fast(float x) {
    float a = fabsf(x);
    float e = __expf(2.0f * a);
    float t = 1.0f - __fdividef(2.0f, e + 1.0f);
    return copysignf(t, x);
}

__global__ void __launch_bounds__(NTHREADS) rnn_fused_kernel(
    const float* __restrict__ x,
    const float* __restrict__ W_ih, const float* __restrict__ b_ih,
    const float* __restrict__ W_hh, const float* __restrict__ b_hh,
    const float* __restrict__ W1,   const float* __restrict__ b1,
    const float* __restrict__ W2,   const float* __restrict__ b2,
    const float* __restrict__ W3,   const float* __restrict__ b3,
    float* __restrict__ out)
{
    extern __shared__ float xs[];  // [2][CHUNK][EPB][XS_STRIDE]
    __shared__ float sW1[144], sW2[144], sb1[12], sb2[12], sW3[12], sb3[1];

    const int tid  = threadIdx.x;
    const int e    = tid >> 2;        // element within block
    const int sub  = tid & 3;         // which 3 h-rows this thread owns
    const int lane = tid & 31;
    const int b    = blockIdx.x * EPB + e;
    const int j0   = sub * 3;

    // MLP weights -> shared (tiny, once)
    for (int i = tid; i < 144; i += NTHREADS) { sW1[i] = W1[i]; sW2[i] = W2[i]; }
    if (tid < 12) { sb1[tid] = b1[tid]; sb2[tid] = b2[tid]; sW3[tid] = W3[tid]; }
    if (tid == 0) sb3[0] = b3[0];

    // Per-thread recurrent weights in registers: 3 rows of W_ih (72) + W_hh (36)
    float wih[3][F_IN], whh[3][H_DIM], bias[3];
    #pragma unroll
    for (int c = 0; c < 3; c++) {
        const int j = j0 + c;
        #pragma unroll
        for (int f = 0; f < F_IN; f++)  wih[c][f] = W_ih[j * F_IN + f];
        #pragma unroll
        for (int k = 0; k < H_DIM; k++) whh[c][k] = W_hh[j * H_DIM + k];
        bias[c] = b_ih[j] + b_hh[j];
    }

    const long xbase = (long)blockIdx.x * EPB * T_LEN * F_IN;

    // Stage a chunk of 8 timesteps for all 32 elements: 1536 x 16B cp.async,
    // 12 per thread, ordered so consecutive threads read contiguous global bytes.
    auto load_chunk = [&](int bufidx, int c) {
        float* dstbuf = xs + bufidx * XS_BUF_FLOATS;
        #pragma unroll
        for (int i = 0; i < 12; i++) {
            int idx = tid + NTHREADS * i;         // 0..1535
            int ee  = idx / 48;                   // element: 48 chunks each (768B contig)
            int r   = idx % 48;
            int tt  = r / 6;
            int q   = r % 6;
            const float* src = x + xbase + ((long)ee * T_LEN + (c * CHUNK + tt)) * F_IN + q * 4;
            unsigned dst = smem_u32(dstbuf + (tt * EPB + ee) * XS_STRIDE + q * 4);
            cp_async16(dst, src);
        }
        cp_commit();
    };

    float h_all[H_DIM];
    #pragma unroll
    for (int k = 0; k < H_DIM; k++) h_all[k] = 0.0f;

    load_chunk(0, 0);

    for (int c = 0; c < NCHUNK; c++) {
        __syncthreads();  // (A) everyone done reading buf[(c+1)&1] (chunk c-1)
        if (c + 1 < NCHUNK) { load_chunk((c + 1) & 1, c + 1); cp_wait<1>(); }
        else                { cp_wait<0>(); }
        __syncthreads();  // (B) buf[c&1] data visible to all threads

        const float* buf = xs + (c & 1) * XS_BUF_FLOATS;
        #pragma unroll
        for (int tt = 0; tt < CHUNK; tt++) {
            const float4* xrow = (const float4*)(buf + (tt * EPB + e) * XS_STRIDE);
            float acc[3] = {bias[0], bias[1], bias[2]};
            // input projection: 72 FMA from 6 conflict-free LDS.128
            #pragma unroll
            for (int q = 0; q < 6; q++) {
                float4 v = xrow[q];
                #pragma unroll
                for (int cc = 0; cc < 3; cc++) {
                    acc[cc] = fmaf(wih[cc][4 * q + 0], v.x, acc[cc]);
                    acc[cc] = fmaf(wih[cc][4 * q + 1], v.y, acc[cc]);
                    acc[cc] = fmaf(wih[cc][4 * q + 2], v.z, acc[cc]);
                    acc[cc] = fmaf(wih[cc][4 * q + 3], v.w, acc[cc]);
                }
            }
            // recurrence: 36 FMA
            #pragma unroll
            for (int k = 0; k < H_DIM; k++) {
                #pragma unroll
                for (int cc = 0; cc < 3; cc++)
                    acc[cc] = fmaf(whh[cc][k], h_all[k], acc[cc]);
            }
            float hl[3];
            #pragma unroll
            for (int cc = 0; cc < 3; cc++) hl[cc] = tanh_fast(acc[cc]);
            // h exchange inside the quad: 12 shfl, no barrier
            const int qbase = lane & ~3;
            #pragma unroll
            for (int s = 0; s < 4; s++) {
                #pragma unroll
                for (int cc = 0; cc < 3; cc++)
                    h_all[s * 3 + cc] = __shfl_sync(0xffffffffu, hl[cc], qbase + s);
            }
        }
    }

    // MLP head: one thread per element (has full h_all via last shuffle)
    if (sub == 0) {
        float o1[H_DIM], o2[H_DIM];
        #pragma unroll
        for (int j = 0; j < H_DIM; j++) {
            float s = sb1[j];
            #pragma unroll
            for (int k = 0; k < H_DIM; k++) s = fmaf(sW1[j * H_DIM + k], h_all[k], s);
            o1[j] = fmaxf(s, 0.0f);
        }
        #pragma unroll
        for (int j = 0; j < H_DIM; j++) {
            float s = sb2[j];
            #pragma unroll
            for (int k = 0; k < H_DIM; k++) s = fmaf(sW2[j * H_DIM + k], o1[k], s);
            o2[j] = fmaxf(s, 0.0f);
        }
        float s = sb3[0];
        #pragma unroll
        for (int k = 0; k < H_DIM; k++) s = fmaf(sW3[k], o2[k], s);
        out[b] = s;
    }
}

extern "C" void kernel_launch(void* const* d_in, const int* in_sizes, int n_in,
                              void* d_out, int out_size) {
    (void)in_sizes; (void)n_in; (void)out_size;
    const float* x    = (const float*)d_in[0];
    const float* W_ih = (const float*)d_in[1];
    const float* b_ih = (const float*)d_in[2];
    const float* W_hh = (const float*)d_in[3];
    const float* b_hh = (const float*)d_in[4];
    const float* W1   = (const float*)d_in[5];
    const float* b1   = (const float*)d_in[6];
    const float* W2   = (const float*)d_in[7];
    const float* b2   = (const float*)d_in[8];
    const float* W3   = (const float*)d_in[9];
    const float* b3   = (const float*)d_in[10];
    float* out = (float*)d_out;

    cudaFuncSetAttribute(rnn_fused_kernel,
                         cudaFuncAttributeMaxDynamicSharedMemorySize, SMEM_BYTES);

    dim3 grid(B_TOT / EPB);   // 256 blocks
    dim3 block(NTHREADS);     // 128 threads
    rnn_fused_kernel<<<grid, block, SMEM_BYTES>>>(
        x, W_ih, b_ih, W_hh, b_hh, W1, b1, W2, b2, W3, b3, out);
}